// round 8
// baseline (speedup 1.0000x reference)
#include <cuda_runtime.h>

// B=4, T=32, C=512, ENC=32, DIM=1024, N_PAIRS=4096
// Output: Re(final_state), float32[4194304], idx = P*1024 + d.

__device__ float2 g_aL[128 * 32];
__device__ float2 g_bL[128 * 32];

__device__ __forceinline__ int imin(int a, int b) { return a < b ? a : b; }

// Complex 2x2 gate G = RY(ty)*RX(tx) as a shfl butterfly inside one warp.
__device__ __forceinline__ float2 gate_shfl_c(float2 v, int lane, int mask,
                                              float tx, float ty) {
    float cx, sx, cy, sy;
    sincosf(0.5f * tx, &sx, &cx);
    sincosf(0.5f * ty, &sy, &cy);
    float ox = __shfl_xor_sync(0xffffffffu, v.x, mask);
    float oy = __shfl_xor_sync(0xffffffffu, v.y, mask);
    bool hi = (lane & mask) != 0;
    // lo: G00=(cycx, sysx)  G01=(-sycx,-cysx)
    // hi: G11=(cycx,-sysx)  G10=( sycx,-cysx)
    float mdx = cy * cx,                 mdy = hi ? -sy * sx : sy * sx;
    float mox = hi ? sy * cx : -sy * cx, moy = -cy * sx;
    float2 r;
    r.x = mdx * v.x - mdy * v.y + mox * ox - moy * oy;
    r.y = mdx * v.y + mdy * v.x + mox * oy + moy * ox;
    return r;
}

// enc = L2norm(x @ W^T + b); then layer-1 gates -> a' (wires 0..4), b' (5..9).
// Reads clamped to declared bounds (defensive; cold path).
__global__ void __launch_bounds__(256) enc_kernel(
    const float* __restrict__ x, const float* __restrict__ W,
    const float* __restrict__ bias, const float* __restrict__ trx,
    const float* __restrict__ try0) {
    int row = imin((int)blockIdx.x, 127);
    __shared__ float part[32][8];
    int tid = threadIdx.x;
    int j = tid >> 3, p = tid & 7;
    int xb = row * 512 + p * 64;
    int wb = j * 512 + p * 64;
    float s = 0.f;
#pragma unroll 16
    for (int k = 0; k < 64; k++)
        s = fmaf(x[imin(xb + k, 65535)], W[imin(wb + k, 16383)], s);
    part[j][p] = s;
    __syncthreads();
    if (tid < 32) {
        int lane = tid;
        float acc = bias[imin(lane, 31)];
#pragma unroll
        for (int q = 0; q < 8; q++) acc += part[lane][q];
        float sq = acc * acc;
#pragma unroll
        for (int o = 16; o; o >>= 1) sq += __shfl_xor_sync(0xffffffffu, sq, o);
        float v = acc * rsqrtf(sq);
        float2 a = make_float2(v, 0.f);
        float2 b = make_float2(v, 0.f);
#pragma unroll
        for (int w = 0; w < 5; w++) {
            int mask = 16 >> w;      // wire w -> bit (4-w)
            a = gate_shfl_c(a, lane, mask, trx[w], try0[w]);
            b = gate_shfl_c(b, lane, mask, trx[w + 5], try0[w + 5]);
        }
        int gi = row * 32 + lane;
        g_aL[gi] = a;
        g_bL[gi] = b;
    }
}

// One warp per pair. Since CNOT ring is a permutation and the final RY layer
// is real, Re(out) = RY_ring(perm(Re(a' (x) b'))). Pure REAL arithmetic:
// Re(a'*b') = re_a*re_b - im_a*im_b, then 10 real butterflies, float store.
__global__ void __launch_bounds__(256) pair_kernel(
    const float* __restrict__ try1, float* __restrict__ out,
    unsigned int n_out_f32) {
    __shared__ float2 a_sm[8][32];
    __shared__ float2 b_sm[8][32];
    __shared__ float2 cs[10];
    int tid = threadIdx.x, wid = tid >> 5, lane = tid & 31;
    if (tid < 10) {
        float c, s;
        sincosf(0.5f * try1[tid], &s, &c);
        cs[tid] = make_float2(c, s);
    }
    int P = imin((int)blockIdx.x * 8 + wid, 4095);
    int b = P >> 10;
    int rest = P & 1023;
    int i = rest >> 5, j = rest & 31;
    a_sm[wid][lane] = g_aL[(b * 32 + i) * 32 + lane];
    b_sm[wid][lane] = g_bL[(b * 32 + j) * 32 + lane];
    __syncthreads();

    // out index d = m*32 + lane. Pre-CNOT source index e:
    //   E[q] = D[q]^D[q+1] (q<=7);  E[8] = D[8]^D[9]^D[0];  E[9] = D[9]^D[0]
    float wv[32];
#pragma unroll
    for (int m = 0; m < 32; m++) {
        int d = (m << 5) | lane;
        int t = d ^ (d >> 1);
        int x1 = ((d >> 9) ^ (d >> 8) ^ d) & 1;
        int x0 = ((d >> 9) ^ d) & 1;
        int e = (t & 0xFF) | (x1 << 8) | (x0 << 9);
        float2 av = a_sm[wid][(e >> 5) & 31];
        float2 bv = b_sm[wid][e & 31];
        wv[m] = av.x * bv.x - av.y * bv.y;     // Re(a'*b')
    }

    // Wires 0..4: in-thread real RY butterflies over bit (4-w) of m.
#pragma unroll
    for (int w = 0; w < 5; w++) {
        float c = cs[w].x, s = cs[w].y;
        const int mask = 16 >> w;
#pragma unroll
        for (int m0 = 0; m0 < 32; m0++) {
            if (m0 & mask) continue;
            int m1 = m0 | mask;
            float v0 = wv[m0], v1 = wv[m1];
            wv[m0] = fmaf(c, v0, -s * v1);
            wv[m1] = fmaf(c, v1,  s * v0);
        }
    }

    // Wires 5..9: cross-lane real RY butterflies over lane bit (9-w).
#pragma unroll
    for (int w = 5; w < 10; w++) {
        float c = cs[w].x, s = cs[w].y;
        const int lm = 16 >> (w - 5);
        float sg = (lane & lm) ? s : -s;
#pragma unroll
        for (int m = 0; m < 32; m++) {
            float o = __shfl_xor_sync(0xffffffffu, wv[m], lm);
            wv[m] = fmaf(c, wv[m], sg * o);
        }
    }

    unsigned int base = (unsigned int)P * 1024u + (unsigned int)lane;
#pragma unroll
    for (int m = 0; m < 32; m++) {
        unsigned int idx = base + (unsigned int)(m << 5);
        if (idx < n_out_f32) out[idx] = wv[m];
    }
}

__global__ void zero_kernel(float* out, unsigned int n_floats) {
    unsigned int i = blockIdx.x * blockDim.x + threadIdx.x;
    if (i < n_floats) out[i] = 0.f;
}

extern "C" void kernel_launch(void* const* d_in, const int* in_sizes, int n_in,
                              void* d_out, int out_size) {
    // Size-based input dispatch (element counts; byte-count fallback).
    long mx = 0;
    for (int i = 0; i < n_in; i++) if (in_sizes[i] > mx) mx = in_sizes[i];
    int div = (mx == 262144) ? 4 : 1;

    const float* x = 0; const float* W = 0; const float* bias = 0;
    const float* th[3] = {0, 0, 0};
    int nth = 0;
    for (int i = 0; i < n_in; i++) {
        long s = in_sizes[i] / div;
        const float* p = (const float*)d_in[i];
        if (s == 65536)      x = p;
        else if (s == 16384) W = p;
        else if (s == 32)    bias = p;
        else if (s == 10 && nth < 3) th[nth++] = p;
    }
    if (!x || !W || !bias || nth < 3) {
        if (n_in >= 6) {   // positional fallback (reference dict order)
            x = (const float*)d_in[0]; W = (const float*)d_in[1];
            bias = (const float*)d_in[2];
            th[0] = (const float*)d_in[3]; th[1] = (const float*)d_in[4];
            th[2] = (const float*)d_in[5];
        } else {
            zero_kernel<<<(out_size + 255) / 256, 256>>>((float*)d_out,
                                                         (unsigned int)out_size);
            return;
        }
    }

    // out_size = 4194304 float32 elements (16 MB): one float per amplitude,
    // the REAL part of the final state. We write every element exactly once.
    enc_kernel<<<128, 256>>>(x, W, bias, th[0], th[1]);
    pair_kernel<<<512, 256>>>(th[2], (float*)d_out, (unsigned int)out_size);
}

// round 9
// speedup vs baseline: 1.4140x; 1.4140x over previous
#include <cuda_runtime.h>

// B=4, T=32, C=512, ENC=32, DIM=1024, N_PAIRS=4096
// Output: Re(final_state), float32[4194304], idx = P*1024 + d.

typedef unsigned long long ull;

__device__ float2 g_aL[128 * 32];
__device__ float2 g_bL[128 * 32];

__device__ __forceinline__ ull pk2(float lo, float hi) {
    ull r; asm("mov.b64 %0, {%1, %2};" : "=l"(r) : "f"(lo), "f"(hi)); return r;
}
__device__ __forceinline__ void unpk2(ull v, float& lo, float& hi) {
    asm("mov.b64 {%0, %1}, %2;" : "=f"(lo), "=f"(hi) : "l"(v));
}
__device__ __forceinline__ ull fma2(ull a, ull b, ull c) {
    ull d; asm("fma.rn.f32x2 %0, %1, %2, %3;" : "=l"(d) : "l"(a), "l"(b), "l"(c)); return d;
}

// Complex 2x2 gate G = RY(ty)*RX(tx) as a shfl butterfly inside one warp.
__device__ __forceinline__ float2 gate_shfl_c(float2 v, int lane, int mask,
                                              float tx, float ty) {
    float cx, sx, cy, sy;
    sincosf(0.5f * tx, &sx, &cx);
    sincosf(0.5f * ty, &sy, &cy);
    float ox = __shfl_xor_sync(0xffffffffu, v.x, mask);
    float oy = __shfl_xor_sync(0xffffffffu, v.y, mask);
    bool hi = (lane & mask) != 0;
    float mdx = cy * cx,                 mdy = hi ? -sy * sx : sy * sx;
    float mox = hi ? sy * cx : -sy * cx, moy = -cy * sx;
    float2 r;
    r.x = mdx * v.x - mdy * v.y + mox * ox - moy * oy;
    r.y = mdx * v.y + mdy * v.x + mox * oy + moy * ox;
    return r;
}

// enc = L2norm(x @ W^T + b); then layer-1 gates -> a' (wires 0..4), b' (5..9).
__global__ void __launch_bounds__(256) enc_kernel(
    const float* __restrict__ x, const float* __restrict__ W,
    const float* __restrict__ bias, const float* __restrict__ trx,
    const float* __restrict__ try0) {
    int row = blockIdx.x;            // 0..127
    __shared__ float part[32][8];
    int tid = threadIdx.x;
    int j = tid >> 3, p = tid & 7;
    const float4* xr = (const float4*)(x + row * 512 + p * 64);
    const float4* wr = (const float4*)(W + j * 512 + p * 64);
    float s = 0.f;
#pragma unroll
    for (int k = 0; k < 16; k++) {
        float4 xv = xr[k], wv = wr[k];
        s = fmaf(xv.x, wv.x, s); s = fmaf(xv.y, wv.y, s);
        s = fmaf(xv.z, wv.z, s); s = fmaf(xv.w, wv.w, s);
    }
    part[j][p] = s;
    __syncthreads();
    if (tid < 32) {
        int lane = tid;
        float acc = bias[lane];
#pragma unroll
        for (int q = 0; q < 8; q++) acc += part[lane][q];
        float sq = acc * acc;
#pragma unroll
        for (int o = 16; o; o >>= 1) sq += __shfl_xor_sync(0xffffffffu, sq, o);
        float v = acc * rsqrtf(sq);
        float2 a = make_float2(v, 0.f);
        float2 b = make_float2(v, 0.f);
#pragma unroll
        for (int w = 0; w < 5; w++) {
            int mask = 16 >> w;      // wire w -> bit (4-w)
            a = gate_shfl_c(a, lane, mask, trx[w], try0[w]);
            b = gate_shfl_c(b, lane, mask, trx[w + 5], try0[w + 5]);
        }
        int gi = row * 32 + lane;
        g_aL[gi] = a;
        g_bL[gi] = b;
    }
}

// Pair kernel: each WARP handles TWO pairs (lo/hi lanes of f32x2 registers).
// Tangent-form butterflies: [c -s; s c] = c*[1 -t; t 1]; global scale
// C = prod(cos) folded into the a-vector at load. One fma2 per butterfly out.
// Block = 128 threads = 4 warps = 8 pairs; grid = 512 blocks = 4096 pairs.
__global__ void __launch_bounds__(128) pair_kernel(
    const float* __restrict__ try1, float* __restrict__ out,
    unsigned int n_out_f32) {
    __shared__ float2 a_s[32];          // row i (shared by whole block), *C
    __shared__ float4 bpair[4][32];     // per warp: {b_j0.re, b_j0.im, b_j1.re, b_j1.im}
    __shared__ float csm[10], tsm[10];
    int tid = threadIdx.x, wid = tid >> 5, lane = tid & 31;

    int Pbase = blockIdx.x * 8;
    int bb = Pbase >> 10;
    int rest = Pbase & 1023;
    int i = rest >> 5;                  // same for all 8 pairs in block
    int jb = rest & 31;                 // j base (multiple of 8)

    if (tid < 10) {
        float c, s;
        sincosf(0.5f * try1[tid], &s, &c);
        csm[tid] = c;
        tsm[tid] = s / c;
    }
    {   // b rows for this warp's two pairs, interleaved for LDS.128
        int j0 = jb + 2 * wid;
        float2 b0 = g_bL[(bb * 32 + j0) * 32 + lane];
        float2 b1 = g_bL[(bb * 32 + j0 + 1) * 32 + lane];
        bpair[wid][lane] = make_float4(b0.x, b0.y, b1.x, b1.y);
    }
    __syncthreads();
    if (tid < 32) {
        float C = csm[0];
#pragma unroll
        for (int k = 1; k < 10; k++) C *= csm[k];
        float2 av = g_aL[(bb * 32 + i) * 32 + tid];
        a_s[tid] = make_float2(av.x * C, av.y * C);
    }
    __syncthreads();

    float tv[10];
#pragma unroll
    for (int k = 0; k < 10; k++) tv[k] = tsm[k];

    // Permutation e(d) is GF(2)-linear: e = lp(lane) ^ mp(m), d = (m<<5)|lane.
    //   lp = ((lane^(lane>>1))&0xF) | (lane&16) | (lane0 * 0x300)
    //   mp = ((m&1)<<4) | ((m^(m>>1))<<5)          (compile-time per m)
    int lp = ((lane ^ (lane >> 1)) & 0xF) | (lane & 16) | ((lane & 1) * 0x300);

    ull wv[32];
#pragma unroll
    for (int m = 0; m < 32; m++) {
        const int mp = ((m & 1) << 4) | ((m ^ (m >> 1)) << 5);
        int e = lp ^ mp;
        float2 a = a_s[e >> 5];
        float4 b4 = bpair[wid][e & 31];
        wv[m] = pk2(a.x * b4.x - a.y * b4.y,    // pair A: Re(a'*b_j0')
                    a.x * b4.z - a.y * b4.w);   // pair B: Re(a'*b_j1')
    }

    // Wires 0..4: in-thread t-form butterflies over bit (4-w) of m.
#pragma unroll
    for (int w = 0; w < 5; w++) {
        float t = tv[w];
        ull tp = pk2(t, t), ntp = pk2(-t, -t);
        const int mask = 16 >> w;
#pragma unroll
        for (int m0 = 0; m0 < 32; m0++) {
            if (m0 & mask) continue;
            int m1 = m0 | mask;
            ull v0 = wv[m0], v1 = wv[m1];
            wv[m0] = fma2(ntp, v1, v0);   // v0 - t*v1
            wv[m1] = fma2(tp, v0, v1);    // v1 + t*v0
        }
    }

    // Wires 5..9: cross-lane t-form butterflies over lane bit (9-w).
#pragma unroll
    for (int w = 0; w < 5; w++) {
        const int lm = 16 >> w;
        float t = tv[5 + w];
        float sg = (lane & lm) ? t : -t;
        ull sp = pk2(sg, sg);
#pragma unroll
        for (int m = 0; m < 32; m++) {
            ull o = __shfl_xor_sync(0xffffffffu, wv[m], lm);
            wv[m] = fma2(sp, o, wv[m]);
        }
    }

    int P0 = Pbase + 2 * wid;
    unsigned int base = (unsigned int)P0 * 1024u + (unsigned int)lane;
    float* op = out + base;
    if ((unsigned int)(P0 + 2) * 1024u <= n_out_f32) {
        // Full-speed path: immediate-offset STG.32, coalesced across lanes.
#pragma unroll
        for (int m = 0; m < 32; m++) {
            float lo, hi; unpk2(wv[m], lo, hi);
            op[m << 5] = lo;
            op[(m << 5) + 1024] = hi;
        }
    } else {
#pragma unroll
        for (int m = 0; m < 32; m++) {
            float lo, hi; unpk2(wv[m], lo, hi);
            unsigned int i0 = base + (unsigned int)(m << 5);
            if (i0 < n_out_f32) op[m << 5] = lo;
            if (i0 + 1024u < n_out_f32) op[(m << 5) + 1024] = hi;
        }
    }
}

__global__ void zero_kernel(float* out, unsigned int n_floats) {
    unsigned int i = blockIdx.x * blockDim.x + threadIdx.x;
    if (i < n_floats) out[i] = 0.f;
}

extern "C" void kernel_launch(void* const* d_in, const int* in_sizes, int n_in,
                              void* d_out, int out_size) {
    long mx = 0;
    for (int i = 0; i < n_in; i++) if (in_sizes[i] > mx) mx = in_sizes[i];
    int div = (mx == 262144) ? 4 : 1;

    const float* x = 0; const float* W = 0; const float* bias = 0;
    const float* th[3] = {0, 0, 0};
    int nth = 0;
    for (int i = 0; i < n_in; i++) {
        long s = in_sizes[i] / div;
        const float* p = (const float*)d_in[i];
        if (s == 65536)      x = p;
        else if (s == 16384) W = p;
        else if (s == 32)    bias = p;
        else if (s == 10 && nth < 3) th[nth++] = p;
    }
    if (!x || !W || !bias || nth < 3) {
        if (n_in >= 6) {
            x = (const float*)d_in[0]; W = (const float*)d_in[1];
            bias = (const float*)d_in[2];
            th[0] = (const float*)d_in[3]; th[1] = (const float*)d_in[4];
            th[2] = (const float*)d_in[5];
        } else {
            zero_kernel<<<(out_size + 255) / 256, 256>>>((float*)d_out,
                                                         (unsigned int)out_size);
            return;
        }
    }

    enc_kernel<<<128, 256>>>(x, W, bias, th[0], th[1]);
    pair_kernel<<<512, 128>>>(th[2], (float*)d_out, (unsigned int)out_size);
}